// round 5
// baseline (speedup 1.0000x reference)
#include <cuda_runtime.h>
#include <cuda_bf16.h>
#include <cstdint>

#define N_USER 50000
#define N_ITEM 100000
#define N_TOT  150000
#define D      64
#define NNZ    2400000
#define B_SZ   4096
#define N_LAYERS 3

#define SCAN_B 1024
#define SCAN_NBLK ((N_TOT + SCAN_B - 1) / SCAN_B)   // 147

#define ROWS_PER_BLK 32
#define LBLK ((N_TOT + ROWS_PER_BLK - 1) / ROWS_PER_BLK)  // 4688

// ---------------- device scratch (allocation-free rule) ----------------
__device__ float g_E0[N_TOT * D];         // ego ping
__device__ float g_E1[N_TOT * D];         // ego pong
__device__ float g_all[N_TOT * 4 * D];    // [ego0 | norm1 | norm2 | norm3]
__device__ int   g_cnt[N_TOT];
__device__ int   g_rowptr[N_TOT + 1];
__device__ int   g_cur[N_TOT];
__device__ int   g_bsum[SCAN_NBLK + 1];
__device__ int2  g_csr[NNZ];              // packed (col, val-bits)

// ---------------------------------------------------------------------------
__global__ void init_kernel(const float* __restrict__ user_emb,
                            const float* __restrict__ item_emb) {
    int i = blockIdx.x * blockDim.x + threadIdx.x;
    if (i >= N_TOT * D) return;
    float v = (i < N_USER * D) ? user_emb[i] : item_emb[i - N_USER * D];
    g_E0[i] = v;
    int row = i >> 6, col = i & 63;
    g_all[row * (4 * D) + col] = v;
    if (col == 0) g_cnt[row] = 0;
}

// ---------------------------------------------------------------------------
// CSR build
// ---------------------------------------------------------------------------
__global__ void hist_kernel(const int* __restrict__ rows) {
    int i = blockIdx.x * blockDim.x + threadIdx.x;
    if (i < NNZ) atomicAdd(&g_cnt[rows[i]], 1);
}

__global__ void scan1_kernel() {
    __shared__ int s[SCAN_B];
    int tid = threadIdx.x;
    int gid = blockIdx.x * SCAN_B + tid;
    int v = (gid < N_TOT) ? g_cnt[gid] : 0;
    s[tid] = v;
    __syncthreads();
    #pragma unroll
    for (int off = 1; off < SCAN_B; off <<= 1) {
        int t = (tid >= off) ? s[tid - off] : 0;
        __syncthreads();
        s[tid] += t;
        __syncthreads();
    }
    if (gid < N_TOT) g_rowptr[gid] = s[tid] - v;
    if (tid == SCAN_B - 1) g_bsum[blockIdx.x] = s[tid];
}

__global__ void scan2_kernel() {
    __shared__ int s[256];
    int tid = threadIdx.x;
    int v = (tid < SCAN_NBLK) ? g_bsum[tid] : 0;
    s[tid] = v;
    __syncthreads();
    #pragma unroll
    for (int off = 1; off < 256; off <<= 1) {
        int t = (tid >= off) ? s[tid - off] : 0;
        __syncthreads();
        s[tid] += t;
        __syncthreads();
    }
    if (tid < SCAN_NBLK) g_bsum[tid] = s[tid] - v;
}

__global__ void scan3_kernel() {
    int gid = blockIdx.x * SCAN_B + threadIdx.x;
    if (gid < N_TOT) {
        g_rowptr[gid] += g_bsum[blockIdx.x];
        g_cur[gid] = 0;
    }
    if (gid == 0) g_rowptr[N_TOT] = NNZ;
}

__global__ void scatter_kernel(const float* __restrict__ vals,
                               const int*   __restrict__ rows,
                               const int*   __restrict__ cols) {
    int i = blockIdx.x * blockDim.x + threadIdx.x;
    if (i >= NNZ) return;
    int r = rows[i];
    int pos = g_rowptr[r] + atomicAdd(&g_cur[r], 1);
    g_csr[pos] = make_int2(cols[i], __float_as_int(vals[i]));
}

// ---------------------------------------------------------------------------
// bf16 split helpers: v -> hi (bf16x2) and lo (bf16x2 residual)
// ---------------------------------------------------------------------------
__device__ __forceinline__ void split2(float2 v, uint32_t& hi, uint32_t& lo) {
    __nv_bfloat162 h = __floats2bfloat162_rn(v.x, v.y);    // x -> low half
    float rx = v.x - __bfloat162float(h.x);
    float ry = v.y - __bfloat162float(h.y);
    __nv_bfloat162 l2 = __floats2bfloat162_rn(rx, ry);
    hi = *reinterpret_cast<uint32_t*>(&h);
    lo = *reinterpret_cast<uint32_t*>(&l2);
}

#define MMA_BF16(C, A0, A1, A2, A3, B0, B1)                                   \
    asm volatile(                                                             \
        "mma.sync.aligned.m16n8k16.row.col.f32.bf16.bf16.f32 "                \
        "{%0,%1,%2,%3}, {%4,%5,%6,%7}, {%8,%9}, {%0,%1,%2,%3};"               \
        : "+f"(C[0]), "+f"(C[1]), "+f"(C[2]), "+f"(C[3])                      \
        : "r"(A0), "r"(A1), "r"(A2), "r"(A3), "r"(B0), "r"(B1))

// ---------------------------------------------------------------------------
// FUSED layer kernel (R3 structure, tensor-core GEMM):
//   Phase 0: stage W' = [Wgc;Wbi] transposed to bf16 hi/lo planes sWT[n][k]
//   Phase 1: CSR SPMM (256 threads, 16/row) -> sA = [L+E | L*E]  (32 x 128)
//   Phase 2: split-bf16 mma.sync GEMM (3-product compensation) -> sC (=sA)
//   Phase 3: epilogue (+2b, leaky-relu, row-norm, stores)
// ---------------------------------------------------------------------------
__global__ void __launch_bounds__(256)
fused_layer_kernel(const float* __restrict__ ego_in,
                   float*       __restrict__ ego_out,
                   const float* __restrict__ Wgc,
                   const float* __restrict__ Wbi,
                   const float* __restrict__ bb,
                   int layer) {
    __shared__ float sA[32 * 128];                 // later aliased as sC[32][64]
    __shared__ __nv_bfloat16 sWThi[64 * 128];      // [n][k]
    __shared__ __nv_bfloat16 sWTlo[64 * 128];      // [n][k]

    int tid = threadIdx.x;
    int rowBase = blockIdx.x * ROWS_PER_BLK;

    // ---- Phase 0: stage W transposed, bf16 hi/lo ----
    {
        #pragma unroll
        for (int p = 0; p < 8; p++) {
            int i4 = p * 256 + tid;                   // float4 index, 2048 total
            float4 w4 = (i4 < 1024) ? ((const float4*)Wgc)[i4]
                                    : ((const float4*)Wbi)[i4 - 1024];
            int base = i4 * 4;
            int k = base >> 6;
            int n = base & 63;
            float wv[4] = {w4.x, w4.y, w4.z, w4.w};
            #pragma unroll
            for (int j = 0; j < 4; j++) {
                __nv_bfloat16 h = __float2bfloat16(wv[j]);
                float lof = wv[j] - __bfloat162float(h);
                sWThi[(n + j) * 128 + k] = h;
                sWTlo[(n + j) * 128 + k] = __float2bfloat16(lof);
            }
        }
    }

    // ---- Phase 1: CSR SPMM, 16 threads/row, 2 passes over 32 rows ----
    {
        int rsub = tid >> 4;            // 0..15
        int c    = (tid & 15) << 2;     // float4 column offset
        #pragma unroll
        for (int pass = 0; pass < 2; pass++) {
            int rl  = pass * 16 + rsub;        // 0..31
            int row = rowBase + rl;
            float4 acc = make_float4(0.f, 0.f, 0.f, 0.f);
            float4 e   = make_float4(0.f, 0.f, 0.f, 0.f);
            if (row < N_TOT) {
                int s0 = g_rowptr[row];
                int e0 = g_rowptr[row + 1];
                int j = s0;
                for (; j + 4 <= e0; j += 4) {
                    int2 a  = g_csr[j];
                    int2 b  = g_csr[j + 1];
                    int2 cc = g_csr[j + 2];
                    int2 dd = g_csr[j + 3];
                    float4 va = __ldg((const float4*)&ego_in[a.x * D + c]);
                    float4 vb = __ldg((const float4*)&ego_in[b.x * D + c]);
                    float4 vc = __ldg((const float4*)&ego_in[cc.x * D + c]);
                    float4 vd = __ldg((const float4*)&ego_in[dd.x * D + c]);
                    float fa = __int_as_float(a.y);
                    float fb = __int_as_float(b.y);
                    float fc = __int_as_float(cc.y);
                    float fd = __int_as_float(dd.y);
                    acc.x += fa * va.x + fb * vb.x + fc * vc.x + fd * vd.x;
                    acc.y += fa * va.y + fb * vb.y + fc * vc.y + fd * vd.y;
                    acc.z += fa * va.z + fb * vb.z + fc * vc.z + fd * vd.z;
                    acc.w += fa * va.w + fb * vb.w + fc * vc.w + fd * vd.w;
                }
                for (; j < e0; j++) {
                    int2 a = g_csr[j];
                    float4 va = __ldg((const float4*)&ego_in[a.x * D + c]);
                    float fa = __int_as_float(a.y);
                    acc.x += fa * va.x; acc.y += fa * va.y;
                    acc.z += fa * va.z; acc.w += fa * va.w;
                }
                e = *(const float4*)&ego_in[row * D + c];
            }
            *(float4*)&sA[rl * 128 + c] =
                make_float4(acc.x + e.x, acc.y + e.y, acc.z + e.z, acc.w + e.w);
            *(float4*)&sA[rl * 128 + 64 + c] =
                make_float4(acc.x * e.x, acc.y * e.y, acc.z * e.z, acc.w * e.w);
        }
    }
    __syncthreads();

    // ---- Phase 2: split-bf16 tensor-core GEMM ----
    // warp w: m-tile = w>>2 (rows 16m..16m+15), n-tiles 2*(w&3), 2*(w&3)+1
    int wid = tid >> 5, lane = tid & 31;
    int gid = lane >> 2, tig = lane & 3;
    int m = wid >> 2;
    int nt0 = (wid & 3) * 2;

    float C0[4] = {0.f, 0.f, 0.f, 0.f};
    float C1[4] = {0.f, 0.f, 0.f, 0.f};

    #pragma unroll
    for (int ks = 0; ks < 8; ks++) {
        int k0 = ks * 16 + tig * 2;
        int r0 = m * 16 + gid;
        float2 aA = *(const float2*)&sA[r0 * 128 + k0];
        float2 aB = *(const float2*)&sA[(r0 + 8) * 128 + k0];
        float2 aC = *(const float2*)&sA[r0 * 128 + k0 + 8];
        float2 aD = *(const float2*)&sA[(r0 + 8) * 128 + k0 + 8];
        uint32_t ah0, al0, ah1, al1, ah2, al2, ah3, al3;
        split2(aA, ah0, al0);
        split2(aB, ah1, al1);
        split2(aC, ah2, al2);
        split2(aD, al3, al3);  // placeholder avoided below
        // (redo aD correctly)
        split2(aD, ah3, al3);

        #pragma unroll
        for (int t = 0; t < 2; t++) {
            int n = (nt0 + t) * 8 + gid;
            const __nv_bfloat16* bph = &sWThi[n * 128 + ks * 16 + tig * 2];
            const __nv_bfloat16* bpl = &sWTlo[n * 128 + ks * 16 + tig * 2];
            uint32_t bh0 = *(const uint32_t*)bph;
            uint32_t bh1 = *(const uint32_t*)(bph + 8);
            uint32_t bl0 = *(const uint32_t*)bpl;
            uint32_t bl1 = *(const uint32_t*)(bpl + 8);
            float* C = (t == 0) ? C0 : C1;
            MMA_BF16(C, ah0, ah1, ah2, ah3, bh0, bh1);   // hi*hi
            MMA_BF16(C, ah0, ah1, ah2, ah3, bl0, bl1);   // hi*lo
            MMA_BF16(C, al0, al1, al2, al3, bh0, bh1);   // lo*hi
        }
    }
    __syncthreads();   // all sA reads done; reuse sA as sC[32][64]

    {
        float* sC = sA;
        int r = m * 16 + gid;
        #pragma unroll
        for (int t = 0; t < 2; t++) {
            const float* C = (t == 0) ? C0 : C1;
            int cb = (nt0 + t) * 8 + tig * 2;
            *(float2*)&sC[r * 64 + cb]        = make_float2(C[0], C[1]);
            *(float2*)&sC[(r + 8) * 64 + cb]  = make_float2(C[2], C[3]);
        }
    }
    __syncthreads();

    // ---- Phase 3: epilogue ----
    {
        const float* sC = sA;
        int ty = tid >> 4;       // rows 2ty, 2ty+1
        int tx = tid & 15;       // cols 4tx..4tx+3
        float4 b4 = *(const float4*)&bb[4 * tx];
        float4 X = *(const float4*)&sC[(2 * ty) * 64 + 4 * tx];
        float4 Y = *(const float4*)&sC[(2 * ty + 1) * 64 + 4 * tx];

        // reference adds b_bi to BOTH branches -> 2*b
        float x0 = X.x + 2.f * b4.x, x1 = X.y + 2.f * b4.y;
        float x2 = X.z + 2.f * b4.z, x3 = X.w + 2.f * b4.w;
        float y0 = Y.x + 2.f * b4.x, y1 = Y.y + 2.f * b4.y;
        float y2 = Y.z + 2.f * b4.z, y3 = Y.w + 2.f * b4.w;

        x0 = x0 > 0.f ? x0 : 0.01f * x0;  x1 = x1 > 0.f ? x1 : 0.01f * x1;
        x2 = x2 > 0.f ? x2 : 0.01f * x2;  x3 = x3 > 0.f ? x3 : 0.01f * x3;
        y0 = y0 > 0.f ? y0 : 0.01f * y0;  y1 = y1 > 0.f ? y1 : 0.01f * y1;
        y2 = y2 > 0.f ? y2 : 0.01f * y2;  y3 = y3 > 0.f ? y3 : 0.01f * y3;

        float ss0 = x0 * x0 + x1 * x1 + x2 * x2 + x3 * x3;
        float ss1 = y0 * y0 + y1 * y1 + y2 * y2 + y3 * y3;
        #pragma unroll
        for (int o = 8; o; o >>= 1) {
            ss0 += __shfl_xor_sync(0xffffffffu, ss0, o);
            ss1 += __shfl_xor_sync(0xffffffffu, ss1, o);
        }
        float inv0 = 1.0f / fmaxf(sqrtf(ss0), 1e-12f);
        float inv1 = 1.0f / fmaxf(sqrtf(ss1), 1e-12f);

        int r0 = rowBase + 2 * ty;
        int r1 = r0 + 1;
        int co = (layer + 1) * D + 4 * tx;
        if (r0 < N_TOT) {
            *(float4*)&ego_out[r0 * D + 4 * tx] = make_float4(x0, x1, x2, x3);
            *(float4*)&g_all[r0 * (4 * D) + co] =
                make_float4(x0 * inv0, x1 * inv0, x2 * inv0, x3 * inv0);
        }
        if (r1 < N_TOT) {
            *(float4*)&ego_out[r1 * D + 4 * tx] = make_float4(y0, y1, y2, y3);
            *(float4*)&g_all[r1 * (4 * D) + co] =
                make_float4(y0 * inv1, y1 * inv1, y2 * inv1, y3 * inv1);
        }
    }
}

// ---------------------------------------------------------------------------
__global__ void gather_kernel(const int* __restrict__ users,
                              const int* __restrict__ pos_items,
                              const int* __restrict__ neg_items,
                              float* __restrict__ out) {
    int idx = blockIdx.x * blockDim.x + threadIdx.x;  // 3*B*256
    if (idx >= 3 * B_SZ * (4 * D)) return;
    int which = idx / (B_SZ * 4 * D);
    int rem   = idx - which * (B_SZ * 4 * D);
    int b = rem >> 8;
    int c = rem & 255;
    int row;
    if (which == 0)      row = users[b];
    else if (which == 1) row = N_USER + pos_items[b];
    else                 row = N_USER + neg_items[b];
    out[idx] = g_all[row * (4 * D) + c];
}

// ---------------------------------------------------------------------------
extern "C" void kernel_launch(void* const* d_in, const int* in_sizes, int n_in,
                              void* d_out, int out_size) {
    const float* user_emb  = (const float*)d_in[0];
    const float* item_emb  = (const float*)d_in[1];
    const float* W_gc      = (const float*)d_in[2];
    const float* W_bi      = (const float*)d_in[3];
    const float* b_bi      = (const float*)d_in[4];
    const float* vals      = (const float*)d_in[5];
    const int*   rows      = (const int*)d_in[6];
    const int*   cols      = (const int*)d_in[7];
    const int*   users     = (const int*)d_in[8];
    const int*   pos_items = (const int*)d_in[9];
    const int*   neg_items = (const int*)d_in[10];
    float* out = (float*)d_out;

    init_kernel<<<(N_TOT * D + 255) / 256, 256>>>(user_emb, item_emb);

    hist_kernel<<<(NNZ + 255) / 256, 256>>>(rows);
    scan1_kernel<<<SCAN_NBLK, SCAN_B>>>();
    scan2_kernel<<<1, 256>>>();
    scan3_kernel<<<SCAN_NBLK, SCAN_B>>>();
    scatter_kernel<<<(NNZ + 255) / 256, 256>>>(vals, rows, cols);

    float* e0; float* e1;
    cudaGetSymbolAddress((void**)&e0, g_E0);
    cudaGetSymbolAddress((void**)&e1, g_E1);

    for (int k = 0; k < N_LAYERS; k++) {
        const float* in   = (k & 1) ? e1 : e0;
        float*       outp = (k & 1) ? e0 : e1;
        fused_layer_kernel<<<LBLK, 256>>>(in, outp,
                                          W_gc + k * D * D,
                                          W_bi + k * D * D,
                                          b_bi + k * D, k);
    }

    gather_kernel<<<(3 * B_SZ * 4 * D + 255) / 256, 256>>>(users, pos_items,
                                                           neg_items, out);
}

// round 6
// speedup vs baseline: 1.9876x; 1.9876x over previous
#include <cuda_runtime.h>
#include <cuda_bf16.h>
#include <cstdint>

#define N_USER 50000
#define N_ITEM 100000
#define N_TOT  150000
#define D      64
#define NNZ    2400000
#define B_SZ   4096
#define N_LAYERS 3

#define SCAN_B 1024
#define SCAN_NBLK ((N_TOT + SCAN_B - 1) / SCAN_B)   // 147

#define ROWS_PER_BLK 32
#define LBLK ((N_TOT + ROWS_PER_BLK - 1) / ROWS_PER_BLK)  // 4688

#define SAP 136   // padded k-stride for sA planes (bf16 elems)

// ---------------- device scratch (allocation-free rule) ----------------
__device__ float g_E0[N_TOT * D];
__device__ float g_E1[N_TOT * D];
__device__ float g_all[N_TOT * 4 * D];
__device__ int   g_cnt[N_TOT];
__device__ int   g_rowptr[N_TOT + 1];
__device__ int   g_cur[N_TOT];
__device__ int   g_bsum[SCAN_NBLK + 1];
__device__ int2  g_csr[NNZ];
__device__ __nv_bfloat16 g_Whi[N_LAYERS][64 * 128];  // [n][k], W'=[Wgc;Wbi]
__device__ __nv_bfloat16 g_Wlo[N_LAYERS][64 * 128];

// ---------------------------------------------------------------------------
__global__ void init_kernel(const float* __restrict__ user_emb,
                            const float* __restrict__ item_emb) {
    int i = blockIdx.x * blockDim.x + threadIdx.x;
    if (i >= N_TOT * D) return;
    float v = (i < N_USER * D) ? user_emb[i] : item_emb[i - N_USER * D];
    g_E0[i] = v;
    int row = i >> 6, col = i & 63;
    g_all[row * (4 * D) + col] = v;
    if (col == 0) g_cnt[row] = 0;
}

// W' -> bf16 hi/lo planes, [n][k] layout. One block per layer.
__global__ void wconv_kernel(const float* __restrict__ Wgc,
                             const float* __restrict__ Wbi) {
    int layer = blockIdx.x;
    const float* wg = Wgc + layer * 4096;
    const float* wb = Wbi + layer * 4096;
    for (int idx = threadIdx.x; idx < 64 * 128; idx += blockDim.x) {
        int n = idx >> 7, k = idx & 127;
        float w = (k < 64) ? wg[k * 64 + n] : wb[(k - 64) * 64 + n];
        __nv_bfloat16 h = __float2bfloat16(w);
        g_Whi[layer][idx] = h;
        g_Wlo[layer][idx] = __float2bfloat16(w - __bfloat162float(h));
    }
}

// ---------------------------------------------------------------------------
// CSR build
// ---------------------------------------------------------------------------
__global__ void hist_kernel(const int* __restrict__ rows) {
    int i = blockIdx.x * blockDim.x + threadIdx.x;
    if (i < NNZ) atomicAdd(&g_cnt[rows[i]], 1);
}

__global__ void scan1_kernel() {
    __shared__ int s[SCAN_B];
    int tid = threadIdx.x;
    int gid = blockIdx.x * SCAN_B + tid;
    int v = (gid < N_TOT) ? g_cnt[gid] : 0;
    s[tid] = v;
    __syncthreads();
    #pragma unroll
    for (int off = 1; off < SCAN_B; off <<= 1) {
        int t = (tid >= off) ? s[tid - off] : 0;
        __syncthreads();
        s[tid] += t;
        __syncthreads();
    }
    if (gid < N_TOT) g_rowptr[gid] = s[tid] - v;
    if (tid == SCAN_B - 1) g_bsum[blockIdx.x] = s[tid];
}

__global__ void scan2_kernel() {
    __shared__ int s[256];
    int tid = threadIdx.x;
    int v = (tid < SCAN_NBLK) ? g_bsum[tid] : 0;
    s[tid] = v;
    __syncthreads();
    #pragma unroll
    for (int off = 1; off < 256; off <<= 1) {
        int t = (tid >= off) ? s[tid - off] : 0;
        __syncthreads();
        s[tid] += t;
        __syncthreads();
    }
    if (tid < SCAN_NBLK) g_bsum[tid] = s[tid] - v;
}

__global__ void scan3_kernel() {
    int gid = blockIdx.x * SCAN_B + threadIdx.x;
    if (gid < N_TOT) {
        g_rowptr[gid] += g_bsum[blockIdx.x];
        g_cur[gid] = 0;
    }
    if (gid == 0) g_rowptr[N_TOT] = NNZ;
}

__global__ void scatter_kernel(const float* __restrict__ vals,
                               const int*   __restrict__ rows,
                               const int*   __restrict__ cols) {
    int i = blockIdx.x * blockDim.x + threadIdx.x;
    if (i >= NNZ) return;
    int r = rows[i];
    int pos = g_rowptr[r] + atomicAdd(&g_cur[r], 1);
    g_csr[pos] = make_int2(cols[i], __float_as_int(vals[i]));
}

// ---------------------------------------------------------------------------
#define MMA_BF16(C, A0, A1, A2, A3, B0, B1)                                   \
    asm volatile(                                                             \
        "mma.sync.aligned.m16n8k16.row.col.f32.bf16.bf16.f32 "                \
        "{%0,%1,%2,%3}, {%4,%5,%6,%7}, {%8,%9}, {%0,%1,%2,%3};"               \
        : "+f"(C[0]), "+f"(C[1]), "+f"(C[2]), "+f"(C[3])                      \
        : "r"(A0), "r"(A1), "r"(A2), "r"(A3), "r"(B0), "r"(B1))

__device__ __forceinline__ uint32_t pack_hi(float a, float b) {
    __nv_bfloat162 h = __floats2bfloat162_rn(a, b);
    return *reinterpret_cast<uint32_t*>(&h);
}

// ---------------------------------------------------------------------------
// FUSED layer kernel:
//   Phase 1: CSR SPMM (256 threads, 16/row) -> sA = [L+E | L*E] split into
//            bf16 hi/lo planes (32 x 136 padded)
//   Phase 2: mma.sync GEMM, 3-product compensation; B frags from global
//   Phase 3: epilogue (+2b, leaky-relu, row-norm, stores)
// ---------------------------------------------------------------------------
__global__ void __launch_bounds__(256)
fused_layer_kernel(const float* __restrict__ ego_in,
                   float*       __restrict__ ego_out,
                   const __nv_bfloat16* __restrict__ Whi,
                   const __nv_bfloat16* __restrict__ Wlo,
                   const float* __restrict__ bb,
                   int layer) {
    __shared__ __nv_bfloat16 sAhi[32 * SAP];
    __shared__ __nv_bfloat16 sAlo[32 * SAP];
    __shared__ float sC[32 * 64];

    int tid = threadIdx.x;
    int rowBase = blockIdx.x * ROWS_PER_BLK;

    // ---- Phase 1: CSR SPMM, 16 threads/row, 2 passes over 32 rows ----
    {
        int rsub = tid >> 4;            // 0..15
        int c    = (tid & 15) << 2;     // float4 column offset
        #pragma unroll
        for (int pass = 0; pass < 2; pass++) {
            int rl  = pass * 16 + rsub;        // 0..31
            int row = rowBase + rl;
            float4 acc = make_float4(0.f, 0.f, 0.f, 0.f);
            float4 e   = make_float4(0.f, 0.f, 0.f, 0.f);
            if (row < N_TOT) {
                int s0 = g_rowptr[row];
                int e0 = g_rowptr[row + 1];
                int j = s0;
                for (; j + 4 <= e0; j += 4) {
                    int2 a  = g_csr[j];
                    int2 b  = g_csr[j + 1];
                    int2 cc = g_csr[j + 2];
                    int2 dd = g_csr[j + 3];
                    float4 va = __ldg((const float4*)&ego_in[a.x * D + c]);
                    float4 vb = __ldg((const float4*)&ego_in[b.x * D + c]);
                    float4 vc = __ldg((const float4*)&ego_in[cc.x * D + c]);
                    float4 vd = __ldg((const float4*)&ego_in[dd.x * D + c]);
                    float fa = __int_as_float(a.y);
                    float fb = __int_as_float(b.y);
                    float fc = __int_as_float(cc.y);
                    float fd = __int_as_float(dd.y);
                    acc.x += fa * va.x + fb * vb.x + fc * vc.x + fd * vd.x;
                    acc.y += fa * va.y + fb * vb.y + fc * vc.y + fd * vd.y;
                    acc.z += fa * va.z + fb * vb.z + fc * vc.z + fd * vd.z;
                    acc.w += fa * va.w + fb * vb.w + fc * vc.w + fd * vd.w;
                }
                for (; j < e0; j++) {
                    int2 a = g_csr[j];
                    float4 va = __ldg((const float4*)&ego_in[a.x * D + c]);
                    float fa = __int_as_float(a.y);
                    acc.x += fa * va.x; acc.y += fa * va.y;
                    acc.z += fa * va.z; acc.w += fa * va.w;
                }
                e = *(const float4*)&ego_in[row * D + c];
            }
            float li[4] = {acc.x + e.x, acc.y + e.y, acc.z + e.z, acc.w + e.w};
            float bi[4] = {acc.x * e.x, acc.y * e.y, acc.z * e.z, acc.w * e.w};

            // split to hi/lo bf16 and store (li at k=c, bi at k=64+c)
            uint32_t h0 = pack_hi(li[0], li[1]);
            uint32_t h1 = pack_hi(li[2], li[3]);
            __nv_bfloat162 hh0 = *reinterpret_cast<__nv_bfloat162*>(&h0);
            __nv_bfloat162 hh1 = *reinterpret_cast<__nv_bfloat162*>(&h1);
            uint32_t l0 = pack_hi(li[0] - __bfloat162float(hh0.x),
                                  li[1] - __bfloat162float(hh0.y));
            uint32_t l1 = pack_hi(li[2] - __bfloat162float(hh1.x),
                                  li[3] - __bfloat162float(hh1.y));
            uint32_t h2 = pack_hi(bi[0], bi[1]);
            uint32_t h3 = pack_hi(bi[2], bi[3]);
            __nv_bfloat162 hh2 = *reinterpret_cast<__nv_bfloat162*>(&h2);
            __nv_bfloat162 hh3 = *reinterpret_cast<__nv_bfloat162*>(&h3);
            uint32_t l2 = pack_hi(bi[0] - __bfloat162float(hh2.x),
                                  bi[1] - __bfloat162float(hh2.y));
            uint32_t l3 = pack_hi(bi[2] - __bfloat162float(hh3.x),
                                  bi[3] - __bfloat162float(hh3.y));

            *(uint2*)&sAhi[rl * SAP + c]      = make_uint2(h0, h1);
            *(uint2*)&sAlo[rl * SAP + c]      = make_uint2(l0, l1);
            *(uint2*)&sAhi[rl * SAP + 64 + c] = make_uint2(h2, h3);
            *(uint2*)&sAlo[rl * SAP + 64 + c] = make_uint2(l2, l3);
        }
    }
    __syncthreads();

    // ---- Phase 2: tensor-core GEMM, B fragments straight from global ----
    int wid = tid >> 5, lane = tid & 31;
    int gid = lane >> 2, tig = lane & 3;
    int m = wid >> 2;                 // 0..1
    int nt0 = (wid & 3) * 2;          // n-tile pair

    float C0[4] = {0.f, 0.f, 0.f, 0.f};
    float C1[4] = {0.f, 0.f, 0.f, 0.f};

    int arow = m * 16 + gid;
    #pragma unroll
    for (int ks = 0; ks < 8; ks++) {
        int k0 = ks * 16 + 2 * tig;
        uint32_t ah0 = *(const uint32_t*)&sAhi[arow * SAP + k0];
        uint32_t ah1 = *(const uint32_t*)&sAhi[(arow + 8) * SAP + k0];
        uint32_t ah2 = *(const uint32_t*)&sAhi[arow * SAP + k0 + 8];
        uint32_t ah3 = *(const uint32_t*)&sAhi[(arow + 8) * SAP + k0 + 8];
        uint32_t al0 = *(const uint32_t*)&sAlo[arow * SAP + k0];
        uint32_t al1 = *(const uint32_t*)&sAlo[(arow + 8) * SAP + k0];
        uint32_t al2 = *(const uint32_t*)&sAlo[arow * SAP + k0 + 8];
        uint32_t al3 = *(const uint32_t*)&sAlo[(arow + 8) * SAP + k0 + 8];

        #pragma unroll
        for (int t = 0; t < 2; t++) {
            int n = (nt0 + t) * 8 + gid;
            const __nv_bfloat16* bph = &Whi[n * 128 + k0];
            const __nv_bfloat16* bpl = &Wlo[n * 128 + k0];
            uint32_t bh0 = __ldg((const uint32_t*)bph);
            uint32_t bh1 = __ldg((const uint32_t*)(bph + 8));
            uint32_t bl0 = __ldg((const uint32_t*)bpl);
            uint32_t bl1 = __ldg((const uint32_t*)(bpl + 8));
            float* C = (t == 0) ? C0 : C1;
            MMA_BF16(C, ah0, ah1, ah2, ah3, bh0, bh1);   // hi*hi
            MMA_BF16(C, ah0, ah1, ah2, ah3, bl0, bl1);   // hi*lo
            MMA_BF16(C, al0, al1, al2, al3, bh0, bh1);   // lo*hi
        }
    }

    // write C fragments to sC
    {
        int r = m * 16 + gid;
        #pragma unroll
        for (int t = 0; t < 2; t++) {
            const float* C = (t == 0) ? C0 : C1;
            int cb = (nt0 + t) * 8 + tig * 2;
            *(float2*)&sC[r * 64 + cb]       = make_float2(C[0], C[1]);
            *(float2*)&sC[(r + 8) * 64 + cb] = make_float2(C[2], C[3]);
        }
    }
    __syncthreads();

    // ---- Phase 3: epilogue ----
    {
        int ty = tid >> 4;       // rows 2ty, 2ty+1
        int tx = tid & 15;       // cols 4tx..4tx+3
        float4 b4 = *(const float4*)&bb[4 * tx];
        float4 X = *(const float4*)&sC[(2 * ty) * 64 + 4 * tx];
        float4 Y = *(const float4*)&sC[(2 * ty + 1) * 64 + 4 * tx];

        // reference adds b_bi to BOTH branches -> 2*b
        float x0 = X.x + 2.f * b4.x, x1 = X.y + 2.f * b4.y;
        float x2 = X.z + 2.f * b4.z, x3 = X.w + 2.f * b4.w;
        float y0 = Y.x + 2.f * b4.x, y1 = Y.y + 2.f * b4.y;
        float y2 = Y.z + 2.f * b4.z, y3 = Y.w + 2.f * b4.w;

        x0 = x0 > 0.f ? x0 : 0.01f * x0;  x1 = x1 > 0.f ? x1 : 0.01f * x1;
        x2 = x2 > 0.f ? x2 : 0.01f * x2;  x3 = x3 > 0.f ? x3 : 0.01f * x3;
        y0 = y0 > 0.f ? y0 : 0.01f * y0;  y1 = y1 > 0.f ? y1 : 0.01f * y1;
        y2 = y2 > 0.f ? y2 : 0.01f * y2;  y3 = y3 > 0.f ? y3 : 0.01f * y3;

        float ss0 = x0 * x0 + x1 * x1 + x2 * x2 + x3 * x3;
        float ss1 = y0 * y0 + y1 * y1 + y2 * y2 + y3 * y3;
        #pragma unroll
        for (int o = 8; o; o >>= 1) {
            ss0 += __shfl_xor_sync(0xffffffffu, ss0, o);
            ss1 += __shfl_xor_sync(0xffffffffu, ss1, o);
        }
        float inv0 = 1.0f / fmaxf(sqrtf(ss0), 1e-12f);
        float inv1 = 1.0f / fmaxf(sqrtf(ss1), 1e-12f);

        int r0 = rowBase + 2 * ty;
        int r1 = r0 + 1;
        int co = (layer + 1) * D + 4 * tx;
        if (r0 < N_TOT) {
            *(float4*)&ego_out[r0 * D + 4 * tx] = make_float4(x0, x1, x2, x3);
            *(float4*)&g_all[r0 * (4 * D) + co] =
                make_float4(x0 * inv0, x1 * inv0, x2 * inv0, x3 * inv0);
        }
        if (r1 < N_TOT) {
            *(float4*)&ego_out[r1 * D + 4 * tx] = make_float4(y0, y1, y2, y3);
            *(float4*)&g_all[r1 * (4 * D) + co] =
                make_float4(y0 * inv1, y1 * inv1, y2 * inv1, y3 * inv1);
        }
    }
}

// ---------------------------------------------------------------------------
__global__ void gather_kernel(const int* __restrict__ users,
                              const int* __restrict__ pos_items,
                              const int* __restrict__ neg_items,
                              float* __restrict__ out) {
    int idx = blockIdx.x * blockDim.x + threadIdx.x;  // 3*B*256
    if (idx >= 3 * B_SZ * (4 * D)) return;
    int which = idx / (B_SZ * 4 * D);
    int rem   = idx - which * (B_SZ * 4 * D);
    int b = rem >> 8;
    int c = rem & 255;
    int row;
    if (which == 0)      row = users[b];
    else if (which == 1) row = N_USER + pos_items[b];
    else                 row = N_USER + neg_items[b];
    out[idx] = g_all[row * (4 * D) + c];
}

// ---------------------------------------------------------------------------
extern "C" void kernel_launch(void* const* d_in, const int* in_sizes, int n_in,
                              void* d_out, int out_size) {
    const float* user_emb  = (const float*)d_in[0];
    const float* item_emb  = (const float*)d_in[1];
    const float* W_gc      = (const float*)d_in[2];
    const float* W_bi      = (const float*)d_in[3];
    const float* b_bi      = (const float*)d_in[4];
    const float* vals      = (const float*)d_in[5];
    const int*   rows      = (const int*)d_in[6];
    const int*   cols      = (const int*)d_in[7];
    const int*   users     = (const int*)d_in[8];
    const int*   pos_items = (const int*)d_in[9];
    const int*   neg_items = (const int*)d_in[10];
    float* out = (float*)d_out;

    init_kernel<<<(N_TOT * D + 255) / 256, 256>>>(user_emb, item_emb);
    wconv_kernel<<<N_LAYERS, 256>>>(W_gc, W_bi);

    hist_kernel<<<(NNZ + 255) / 256, 256>>>(rows);
    scan1_kernel<<<SCAN_NBLK, SCAN_B>>>();
    scan2_kernel<<<1, 256>>>();
    scan3_kernel<<<SCAN_NBLK, SCAN_B>>>();
    scatter_kernel<<<(NNZ + 255) / 256, 256>>>(vals, rows, cols);

    float* e0; float* e1;
    cudaGetSymbolAddress((void**)&e0, g_E0);
    cudaGetSymbolAddress((void**)&e1, g_E1);
    __nv_bfloat16* whi; __nv_bfloat16* wlo;
    cudaGetSymbolAddress((void**)&whi, g_Whi);
    cudaGetSymbolAddress((void**)&wlo, g_Wlo);

    for (int k = 0; k < N_LAYERS; k++) {
        const float* in   = (k & 1) ? e1 : e0;
        float*       outp = (k & 1) ? e0 : e1;
        fused_layer_kernel<<<LBLK, 256>>>(in, outp,
                                          whi + k * 64 * 128,
                                          wlo + k * 64 * 128,
                                          b_bi + k * D, k);
    }

    gather_kernel<<<(3 * B_SZ * 4 * D + 255) / 256, 256>>>(users, pos_items,
                                                           neg_items, out);
}